// round 5
// baseline (speedup 1.0000x reference)
#include <cuda_runtime.h>
#include <cstdint>

#define SEQ   2048
#define HID   512
#define TAPS  64
#define SC    64       // seq rows per CTA
#define UGRP  8        // rows per inner group
#define HTAPS 32       // taps per thread-half
#define WSPAN (HTAPS + UGRP - 1)   // 39 live window rows per half
#define NPAIR 128      // channel pairs per channel-group
#define HBUF_PAIRS 256 // 512 channels as u64 pairs per row

typedef unsigned long long u64;

__device__ __forceinline__ u64 fma2(u64 a, u64 b, u64 c) {
    u64 d;
    asm("fma.rn.f32x2 %0, %1, %2, %3;" : "=l"(d) : "l"(a), "l"(b), "l"(c));
    return d;
}
__device__ __forceinline__ u64 add2(u64 a, u64 b) {
    u64 d;
    asm("add.rn.f32x2 %0, %1, %2;" : "=l"(d) : "l"(a), "l"(b));
    return d;
}
__device__ __forceinline__ float lo32(u64 v) { return __uint_as_float((unsigned)v); }
__device__ __forceinline__ float hi32(u64 v) { return __uint_as_float((unsigned)(v >> 32)); }
__device__ __forceinline__ u64 pack2(float l, float h) {
    return ((u64)__float_as_uint(h) << 32) | (u64)__float_as_uint(l);
}

// Fused circular depthwise conv (64 taps, f32x2) + residual + LayerNorm.
// 512 threads = 128 channel-pairs x 2 tap-halves x (weights from smem).
// Two 256-channel passes. smem: hbuf 128KB + part 16KB + wsm 64KB = 208KB.
extern __shared__ u64 dsm[];

__global__ __launch_bounds__(512, 1) void fconv_ln_kernel(
    const float* __restrict__ x,
    const float* __restrict__ w,
    const float* __restrict__ gamma,
    const float* __restrict__ beta,
    float* __restrict__ out)
{
    u64* hbuf = dsm;                                   // [SC][HBUF_PAIRS]
    u64* part = dsm + SC * HBUF_PAIRS;                 // [2][UGRP][NPAIR]
    u64* wsm  = part + 2 * UGRP * NPAIR;               // [TAPS][NPAIR]

    const int tid = threadIdx.x;
    const int p   = tid & (NPAIR - 1);   // channel pair within group
    const int h   = tid >> 8;            // tap half (tid/256): taps [32h, 32h+32)
    const int b   = blockIdx.y;
    const int s0  = blockIdx.x * SC;

    const float ks = 0.022097086912079608f;   // 1/sqrt(2048)
    const u64 sc2 = pack2(ks, ks);

    const u64* __restrict__ wg = reinterpret_cast<const u64*>(w);  // [TAPS][256]

#pragma unroll 1
    for (int cg = 0; cg < 2; ++cg) {
        const int c = cg * 256 + p * 2;
        const u64* __restrict__ xb =
            reinterpret_cast<const u64*>(x + (size_t)b * (SEQ * HID) + c);
        const int slotc = cg * NPAIR + p;

        // Stage this channel-group's weights: wsm[t][pp] = w[t, cg*256 + 2pp]
        __syncthreads();   // protect wsm reuse across cg iterations
#pragma unroll
        for (int i = 0; i < (TAPS * NPAIR) / 512; ++i) {
            int idx = tid + i * 512;
            wsm[idx] = wg[(idx >> 7) * 256 + cg * NPAIR + (idx & (NPAIR - 1))];
        }

        // Window: win[i] = x[(s0 - 32h - 31 + i) mod SEQ], i in [0,39)
        u64 win[WSPAN];
#pragma unroll
        for (int i = 0; i < WSPAN; ++i) {
            int row = (s0 + SEQ - HTAPS * h - (HTAPS - 1) + i) & (SEQ - 1);
            win[i] = xb[row * (HID / 2)];
        }
        __syncthreads();   // wsm ready

#pragma unroll 1
        for (int g = 0; g < SC / UGRP; ++g) {
            const int sb = s0 + g * UGRP;
            const int rl = g * UGRP;
            const int buf = g & 1;

            // Prefetch the next UGRP window rows.
            u64 nxt[UGRP];
#pragma unroll
            for (int i = 0; i < UGRP; ++i) {
                int row = (sb + SEQ - HTAPS * h + UGRP + i) & (SEQ - 1);
                nxt[i] = xb[row * (HID / 2)];
            }

            // 32-tap partials: acc[j] = sum_t wsm[t+32h][p] * win[31+j-t]
            u64 acc[UGRP];
#pragma unroll
            for (int j = 0; j < UGRP; ++j) acc[j] = 0ull;
            const u64* wrow = wsm + (HTAPS * h) * NPAIR + p;
#pragma unroll 4
            for (int t = 0; t < HTAPS; ++t) {
                const u64 wt = wrow[t * NPAIR];
#pragma unroll
                for (int j = 0; j < UGRP; ++j)
                    acc[j] = fma2(wt, win[HTAPS - 1 + j - t], acc[j]);
            }

            if (h) {
                u64* pp = part + (buf * UGRP) * NPAIR + p;
#pragma unroll
                for (int j = 0; j < UGRP; ++j) pp[j * NPAIR] = acc[j];
            }
            __syncthreads();
            if (!h) {
                const u64* pp = part + (buf * UGRP) * NPAIR + p;
#pragma unroll
                for (int j = 0; j < UGRP; ++j) {
                    u64 tot = add2(acc[j], pp[j * NPAIR]);
                    // residual = x[sb+j] = win[31+j] for half 0
                    hbuf[(rl + j) * HBUF_PAIRS + slotc] =
                        fma2(tot, sc2, win[HTAPS - 1 + j]);
                }
            }

            // Slide window by UGRP.
#pragma unroll
            for (int i = 0; i < WSPAN - UGRP; ++i) win[i] = win[i + UGRP];
#pragma unroll
            for (int i = 0; i < UGRP; ++i) win[WSPAN - UGRP + i] = nxt[i];
        }
    }
    __syncthreads();

    // ---- LayerNorm epilogue: 16 warps, 4 rows each ----
    const int wid  = tid >> 5;
    const int lane = tid & 31;

    u64 g8[8], b8[8];
#pragma unroll
    for (int k = 0; k < 8; ++k) {
        g8[k] = reinterpret_cast<const u64*>(gamma)[lane + 32 * k];
        b8[k] = reinterpret_cast<const u64*>(beta)[lane + 32 * k];
    }

    float* __restrict__ ob = out + (size_t)b * (SEQ * HID) + (size_t)s0 * HID;

#pragma unroll 1
    for (int rr = 0; rr < SC / 16; ++rr) {
        const int r = wid + rr * 16;
        u64 v[8];
        float s = 0.f, qq = 0.f;
#pragma unroll
        for (int k = 0; k < 8; ++k) {
            v[k] = hbuf[r * HBUF_PAIRS + lane + 32 * k];
            float a = lo32(v[k]), bb = hi32(v[k]);
            s += a + bb;
            qq += a * a + bb * bb;
        }
#pragma unroll
        for (int o = 16; o > 0; o >>= 1) {
            s  += __shfl_xor_sync(0xFFFFFFFFu, s, o);
            qq += __shfl_xor_sync(0xFFFFFFFFu, qq, o);
        }
        const float mean = s * (1.0f / HID);
        const float var  = qq * (1.0f / HID) - mean * mean;
        const float inv  = rsqrtf(var + 1e-12f);

        u64* __restrict__ orow = reinterpret_cast<u64*>(ob + r * HID);
#pragma unroll
        for (int k = 0; k < 8; ++k) {
            float a  = (lo32(v[k]) - mean) * inv;
            float bb = (hi32(v[k]) - mean) * inv;
            orow[lane + 32 * k] =
                pack2(lo32(g8[k]) * a + lo32(b8[k]),
                      hi32(g8[k]) * bb + hi32(b8[k]));
        }
    }
}

extern "C" void kernel_launch(void* const* d_in, const int* in_sizes, int n_in,
                              void* d_out, int out_size)
{
    const float* x     = (const float*)d_in[0];   // [B, 2048, 512] f32
    const float* w     = (const float*)d_in[1];   // [1, 64, 512]   f32
    const float* gamma = (const float*)d_in[2];   // [512]          f32
    const float* beta  = (const float*)d_in[3];   // [512]          f32
    float* out = (float*)d_out;

    const int B = in_sizes[0] / (SEQ * HID);
    const int smem =
        (SC * HBUF_PAIRS + 2 * UGRP * NPAIR + TAPS * NPAIR) * sizeof(u64); // 208KB

    static bool attr_set = false;
    if (!attr_set) {
        cudaFuncSetAttribute(fconv_ln_kernel,
                             cudaFuncAttributeMaxDynamicSharedMemorySize, smem);
        attr_set = true;
    }

    dim3 grid(SEQ / SC, B);   // (32, B)
    fconv_ln_kernel<<<grid, 512, smem>>>(x, w, gamma, beta, out);
}

// round 6
// speedup vs baseline: 1.8197x; 1.8197x over previous
#include <cuda_runtime.h>
#include <cstdint>

#define SEQ   2048
#define HID   512
#define TAPS  64
#define SC    64       // seq rows per CTA
#define UGRP  8        // rows per inner group
#define HTAPS 32       // taps per lane-half
#define WSPAN (HTAPS + UGRP - 1)   // 39 live window rows per half
#define HBUF_PAIRS 256 // 512 channels as u64 pairs per row

typedef unsigned long long u64;

__device__ __forceinline__ u64 fma2(u64 a, u64 b, u64 c) {
    u64 d;
    asm("fma.rn.f32x2 %0, %1, %2, %3;" : "=l"(d) : "l"(a), "l"(b), "l"(c));
    return d;
}
__device__ __forceinline__ u64 add2(u64 a, u64 b) {
    u64 d;
    asm("add.rn.f32x2 %0, %1, %2;" : "=l"(d) : "l"(a), "l"(b));
    return d;
}
__device__ __forceinline__ float lo32(u64 v) { return __uint_as_float((unsigned)v); }
__device__ __forceinline__ float hi32(u64 v) { return __uint_as_float((unsigned)(v >> 32)); }
__device__ __forceinline__ u64 pack2(float l, float h) {
    return ((u64)__float_as_uint(h) << 32) | (u64)__float_as_uint(l);
}

// Fused circular depthwise conv (64 taps, f32x2) + residual + LayerNorm.
// 256 threads = 8 warps; each warp owns 16 channel-pairs; within a warp,
// lanes 0-15 compute taps 0..31 and lanes 16-31 taps 32..63 for the SAME
// pairs. Tap-halves combine via shfl_xor(16) -> NO barrier in the conv loop.
// Two 256-channel passes fill a 128KB smem hbuf; LN epilogue normalizes.
extern __shared__ u64 hbuf[];   // [SC][HBUF_PAIRS] = 128 KB

__global__ __launch_bounds__(256, 1) void fconv_ln_kernel(
    const float* __restrict__ x,
    const float* __restrict__ w,
    const float* __restrict__ gamma,
    const float* __restrict__ beta,
    float* __restrict__ out)
{
    const int tid  = threadIdx.x;
    const int wid  = tid >> 5;
    const int lane = tid & 31;
    const int h    = lane >> 4;              // tap half: taps [32h, 32h+32)
    const int pidx = wid * 16 + (lane & 15); // pair index in [0,128)
    const int b    = blockIdx.y;
    const int s0   = blockIdx.x * SC;

    const float ks = 0.022097086912079608f;  // 1/sqrt(2048)
    const u64 sc2 = pack2(ks, ks);

#pragma unroll 1
    for (int cg = 0; cg < 2; ++cg) {
        const int c = cg * 256 + pidx * 2;
        const u64* __restrict__ xb =
            reinterpret_cast<const u64*>(x + (size_t)b * (SEQ * HID) + c);
        const int slotc = cg * 128 + pidx;

        // This half's 32 tap-weights for this channel pair (registers).
        u64 wr[HTAPS];
#pragma unroll
        for (int k = 0; k < HTAPS; ++k)
            wr[k] = *reinterpret_cast<const u64*>(w + (k + HTAPS * h) * HID + c);

        // Window: win[i] = x[(s0 - 32h - 31 + i) mod SEQ], i in [0,39)
        u64 win[WSPAN];
#pragma unroll
        for (int i = 0; i < WSPAN; ++i) {
            int row = (s0 + SEQ - HTAPS * h - (HTAPS - 1) + i) & (SEQ - 1);
            win[i] = xb[row * (HID / 2)];
        }

#pragma unroll 1
        for (int g = 0; g < SC / UGRP; ++g) {
            const int sb = s0 + g * UGRP;
            const int rl = g * UGRP;

            // Prefetch next UGRP window rows (hidden under this group's FMAs).
            u64 nxt[UGRP];
#pragma unroll
            for (int i = 0; i < UGRP; ++i) {
                int row = (sb + SEQ - HTAPS * h + UGRP + i) & (SEQ - 1);
                nxt[i] = xb[row * (HID / 2)];
            }

            // 32-tap partials: acc[j] = sum_t wr[t] * win[31+j-t]
            u64 acc[UGRP];
#pragma unroll
            for (int j = 0; j < UGRP; ++j) acc[j] = 0ull;
#pragma unroll 4
            for (int t = 0; t < HTAPS; ++t) {
#pragma unroll
                for (int j = 0; j < UGRP; ++j)
                    acc[j] = fma2(wr[t], win[HTAPS - 1 + j - t], acc[j]);
            }

            // Combine tap halves within the warp; lanes 0-15 hold the result.
#pragma unroll
            for (int j = 0; j < UGRP; ++j) {
                u64 other = __shfl_xor_sync(0xFFFFFFFFu, acc[j], 16);
                u64 tot   = add2(acc[j], other);
                if (h == 0) {
                    // residual = x[sb+j] = win[31+j] for half 0
                    hbuf[(rl + j) * HBUF_PAIRS + slotc] =
                        fma2(tot, sc2, win[HTAPS - 1 + j]);
                }
            }

            // Slide window by UGRP.
#pragma unroll
            for (int i = 0; i < WSPAN - UGRP; ++i) win[i] = win[i + UGRP];
#pragma unroll
            for (int i = 0; i < UGRP; ++i) win[WSPAN - UGRP + i] = nxt[i];
        }
    }
    __syncthreads();   // hbuf complete -> LN epilogue

    // ---- LayerNorm epilogue: 8 warps, 8 rows each ----
    u64 g8[8], b8[8];
#pragma unroll
    for (int k = 0; k < 8; ++k) {
        g8[k] = reinterpret_cast<const u64*>(gamma)[lane + 32 * k];
        b8[k] = reinterpret_cast<const u64*>(beta)[lane + 32 * k];
    }

    float* __restrict__ ob = out + (size_t)b * (SEQ * HID) + (size_t)s0 * HID;

#pragma unroll 1
    for (int rr = 0; rr < SC / 8; ++rr) {
        const int r = wid + rr * 8;
        u64 v[8];
        float s = 0.f, qq = 0.f;
#pragma unroll
        for (int k = 0; k < 8; ++k) {
            v[k] = hbuf[r * HBUF_PAIRS + lane + 32 * k];
            float a = lo32(v[k]), bb = hi32(v[k]);
            s  += a + bb;
            qq += a * a + bb * bb;
        }
#pragma unroll
        for (int o = 16; o > 0; o >>= 1) {
            s  += __shfl_xor_sync(0xFFFFFFFFu, s, o);
            qq += __shfl_xor_sync(0xFFFFFFFFu, qq, o);
        }
        const float mean = s * (1.0f / HID);
        const float var  = qq * (1.0f / HID) - mean * mean;
        const float inv  = rsqrtf(var + 1e-12f);

        u64* __restrict__ orow = reinterpret_cast<u64*>(ob + r * HID);
#pragma unroll
        for (int k = 0; k < 8; ++k) {
            float a  = (lo32(v[k]) - mean) * inv;
            float bb = (hi32(v[k]) - mean) * inv;
            orow[lane + 32 * k] =
                pack2(lo32(g8[k]) * a + lo32(b8[k]),
                      hi32(g8[k]) * bb + hi32(b8[k]));
        }
    }
}

extern "C" void kernel_launch(void* const* d_in, const int* in_sizes, int n_in,
                              void* d_out, int out_size)
{
    const float* x     = (const float*)d_in[0];   // [B, 2048, 512] f32
    const float* w     = (const float*)d_in[1];   // [1, 64, 512]   f32
    const float* gamma = (const float*)d_in[2];   // [512]          f32
    const float* beta  = (const float*)d_in[3];   // [512]          f32
    float* out = (float*)d_out;

    const int B = in_sizes[0] / (SEQ * HID);
    const int smem = SC * HBUF_PAIRS * sizeof(u64);   // 128 KB

    static bool attr_set = false;
    if (!attr_set) {
        cudaFuncSetAttribute(fconv_ln_kernel,
                             cudaFuncAttributeMaxDynamicSharedMemorySize, smem);
        attr_set = true;
    }

    dim3 grid(SEQ / SC, B);   // (32, B)
    fconv_ln_kernel<<<grid, 256, smem>>>(x, w, gamma, beta, out);
}

// round 8
// speedup vs baseline: 4.3175x; 2.3727x over previous
#include <cuda_runtime.h>
#include <cstdint>

#define SEQ   2048
#define HID   512
#define TAPS  64
#define SC    64        // seq rows per CTA
#define UGRP  8         // rows per group
#define NPAIR 256       // u64 channel-pairs per row (= threads)
#define RING  80        // ring rows in smem

typedef unsigned long long u64;

__device__ __forceinline__ u64 fma2(u64 a, u64 b, u64 c) {
    u64 d;
    asm("fma.rn.f32x2 %0, %1, %2, %3;" : "=l"(d) : "l"(a), "l"(b), "l"(c));
    return d;
}
__device__ __forceinline__ float lo32(u64 v) { return __uint_as_float((unsigned)v); }
__device__ __forceinline__ float hi32(u64 v) { return __uint_as_float((unsigned)(v >> 32)); }
__device__ __forceinline__ u64 pack2(float l, float h) {
    return ((u64)__float_as_uint(h) << 32) | (u64)__float_as_uint(l);
}

#define CP8(dst_u32, src_ptr) \
    asm volatile("cp.async.ca.shared.global [%0], [%1], 8;" :: "r"(dst_u32), "l"(src_ptr))
#define CPCOMMIT() asm volatile("cp.async.commit_group;" ::: "memory")
#define CPWAIT0()  asm volatile("cp.async.wait_group 0;"  ::: "memory")

// Fused circular depthwise conv (64 taps, f32x2) + residual + LayerNorm.
// 256 threads = 256 channel-pairs (all 512 channels). Each thread computes all
// 64 taps from a cp.async-fed smem input ring via a static 8-register band.
// No tap-split, no combine. LN fused per 8-row group with shfl+smem reduce.
extern __shared__ u64 ring[];   // [RING][NPAIR] + red[8][8] float2 + fin[8] float2

__global__ __launch_bounds__(256, 1) void fconv_ln_kernel(
    const float* __restrict__ x,
    const float* __restrict__ w,
    const float* __restrict__ gamma,
    const float* __restrict__ beta,
    float* __restrict__ out)
{
    const int tid  = threadIdx.x;
    const int lane = tid & 31;
    const int widx = tid >> 5;
    const int b    = blockIdx.y;
    const int s0   = blockIdx.x * SC;

    float2* red = reinterpret_cast<float2*>(ring + RING * NPAIR);  // [8 rows][8 warps]
    float2* fin = red + 64;                                        // [8 rows]

    const u64* __restrict__ xb =
        reinterpret_cast<const u64*>(x) + (size_t)b * SEQ * NPAIR;
    u64* __restrict__ op =
        reinterpret_cast<u64*>(out) + ((size_t)b * SEQ + s0) * NPAIR + tid;

    const unsigned rbase = (unsigned)__cvta_generic_to_shared(ring);

    // Initial fill: rows s0-63 .. s0+7  ->  ring slots 1..71 (L = row - s0 + 64)
#pragma unroll 1
    for (int i = 0; i < 71; ++i) {
        int rowg = (s0 - 63 + i + SEQ) & (SEQ - 1);
        CP8(rbase + (unsigned)(((i + 1) * NPAIR + tid) * 8),
            xb + (size_t)rowg * NPAIR + tid);
    }
    CPCOMMIT();

    // Weights (64 taps for this channel pair), gamma, beta — overlap with fill.
    u64 wr[TAPS];
#pragma unroll
    for (int t = 0; t < TAPS; ++t)
        wr[t] = reinterpret_cast<const u64*>(w)[t * NPAIR + tid];
    const u64 g2 = reinterpret_cast<const u64*>(gamma)[tid];
    const u64 b2 = reinterpret_cast<const u64*>(beta)[tid];

    const float ksc = 0.022097086912079608f;   // 1/sqrt(2048)
    const u64 sc2 = pack2(ksc, ksc);

#pragma unroll 1
    for (int g = 0; g < SC / UGRP; ++g) {
        CPWAIT0();
        __syncthreads();   // sync0: prefetched rows visible; old slots free to read

        // Band init: rows sb..sb+7 live at contiguous slots sli..sli+7.
        int sli = 8 * g + 64; if (sli >= RING) sli -= RING;
        u64 band[8];
#pragma unroll
        for (int i = 0; i < 8; ++i) band[i] = ring[(sli + i) * NPAIR + tid];

        u64 acc[8];
#pragma unroll
        for (int j = 0; j < 8; ++j) acc[j] = 0ull;

        // Descending history stream: slot of row sb-1-t, t = 0..62.
        int sl = 8 * g + 63; if (sl >= RING) sl -= RING;
#pragma unroll
        for (int t = 0; t < TAPS; ++t) {
            u64 nv = 0ull;
            if (t < TAPS - 1) {
                nv = ring[sl * NPAIR + tid];
                sl = (sl == 0) ? (RING - 1) : (sl - 1);
            }
#pragma unroll
            for (int j = 0; j < 8; ++j)
                acc[j] = fma2(wr[t], band[(j - t) & 7], acc[j]);
            if (t < TAPS - 1) band[(7 - t) & 7] = nv;   // append row sb-1-t
        }

        // Scale + residual (x[sb+j] re-read from ring at slots sli..sli+7).
#pragma unroll
        for (int j = 0; j < 8; ++j)
            acc[j] = fma2(acc[j], sc2, ring[(sli + j) * NPAIR + tid]);

        // ---- LayerNorm, stage 1: per-warp partial sums per row ----
#pragma unroll
        for (int j = 0; j < 8; ++j) {
            float a = lo32(acc[j]), c = hi32(acc[j]);
            float s = a + c, q = a * a + c * c;
#pragma unroll
            for (int o = 16; o > 0; o >>= 1) {
                s += __shfl_xor_sync(0xFFFFFFFFu, s, o);
                q += __shfl_xor_sync(0xFFFFFFFFu, q, o);
            }
            if (lane == 0) red[j * 8 + widx] = make_float2(s, q);
        }
        __syncthreads();   // sync1: red ready; all ring reads of this group done

        // Prefetch next group's rows (safe: overwrites rows older than needed).
        if (g < SC / UGRP - 1) {
            int slp = 8 * g + 72; if (slp >= RING) slp -= RING;
#pragma unroll
            for (int i = 0; i < 8; ++i) {
                int rowg = (s0 + 8 * g + 8 + i) & (SEQ - 1);
                CP8(rbase + (unsigned)(((slp + i) * NPAIR + tid) * 8),
                    xb + (size_t)rowg * NPAIR + tid);
            }
        }
        CPCOMMIT();

        // ---- LayerNorm, stage 2: warp w finalizes row w ----
        {
            float2 pr = red[widx * 8 + (lane & 7)];
            float s = pr.x, q = pr.y;
#pragma unroll
            for (int o = 4; o > 0; o >>= 1) {
                s += __shfl_xor_sync(0xFFFFFFFFu, s, o);
                q += __shfl_xor_sync(0xFFFFFFFFu, q, o);
            }
            if (lane == 0) {
                float mean = s * (1.0f / HID);
                float var  = q * (1.0f / HID) - mean * mean;
                fin[widx] = make_float2(mean, rsqrtf(var + 1e-12f));
            }
        }
        __syncthreads();   // sync2: fin ready

        // Normalize + write out (coalesced 2KB per row).
#pragma unroll
        for (int j = 0; j < 8; ++j) {
            float2 mi = fin[j];
            float a = (lo32(acc[j]) - mi.x) * mi.y;
            float c = (hi32(acc[j]) - mi.x) * mi.y;
            op[(8 * g + j) * NPAIR] =
                pack2(lo32(g2) * a + lo32(b2), hi32(g2) * c + hi32(b2));
        }
    }
}

extern "C" void kernel_launch(void* const* d_in, const int* in_sizes, int n_in,
                              void* d_out, int out_size)
{
    const float* x     = (const float*)d_in[0];   // [B, 2048, 512] f32
    const float* w     = (const float*)d_in[1];   // [1, 64, 512]   f32
    const float* gamma = (const float*)d_in[2];   // [512]          f32
    const float* beta  = (const float*)d_in[3];   // [512]          f32
    float* out = (float*)d_out;

    const int B = in_sizes[0] / (SEQ * HID);
    const int smem = RING * NPAIR * 8 + 64 * 8 + 8 * 8;   // ring + red + fin ≈ 160.6KB

    static bool attr_set = false;
    if (!attr_set) {
        cudaFuncSetAttribute(fconv_ln_kernel,
                             cudaFuncAttributeMaxDynamicSharedMemorySize, smem);
        attr_set = true;
    }

    dim3 grid(SEQ / SC, B);   // (32, B)
    fconv_ln_kernel<<<grid, 256, smem>>>(x, w, gamma, beta, out);
}